// round 2
// baseline (speedup 1.0000x reference)
#include <cuda_runtime.h>
#include <math.h>
#include <stdint.h>

// Problem dims
#define B_  256
#define T_  512
#define F_  256
#define H_  1024
#define C_  128

// Tiling
#define NCTA 128     // 4 m-blocks x 32 h-blocks
#define NTH  256
#define MT   64      // batch rows per CTA
#define HB   32      // hidden units per CTA (-> 128 gate cols)
#define KT   32      // K tile

// Persistent scratch (no allocations allowed)
__device__ __align__(16) float g_h1[2][B_][H_];
__device__ __align__(16) float g_h2[2][B_][H_];
__device__ unsigned g_cnt = 0;
__device__ volatile unsigned g_gen = 0;

__device__ __forceinline__ void grid_barrier() {
    __syncthreads();
    if (threadIdx.x == 0) {
        unsigned my = g_gen;
        __threadfence();
        if (atomicAdd(&g_cnt, 1u) == NCTA - 1) {
            g_cnt = 0;
            __threadfence();
            g_gen = my + 1;
        } else {
            while (g_gen == my) { }
            __threadfence();
        }
    }
    __syncthreads();
}

__device__ __forceinline__ unsigned f2tf32(float x) {
    unsigned r;
    asm("cvt.rna.tf32.f32 %0, %1;" : "=r"(r) : "f"(x));
    return r;
}

__device__ __forceinline__ uint4 cvt4(float4 v) {
    uint4 t;
    t.x = f2tf32(v.x); t.y = f2tf32(v.y); t.z = f2tf32(v.z); t.w = f2tf32(v.w);
    return t;
}

__device__ __forceinline__ void mma_tf32(float* c, const unsigned* a, unsigned b0, unsigned b1) {
    asm volatile(
        "mma.sync.aligned.m16n8k8.row.col.f32.tf32.tf32.f32 "
        "{%0,%1,%2,%3}, {%4,%5,%6,%7}, {%8,%9}, {%0,%1,%2,%3};"
        : "+f"(c[0]), "+f"(c[1]), "+f"(c[2]), "+f"(c[3])
        : "r"(a[0]), "r"(a[1]), "r"(a[2]), "r"(a[3]), "r"(b0), "r"(b1));
}

__device__ __forceinline__ float sigmoidf_(float x) { return 1.f / (1.f + expf(-x)); }

// One LSTM layer for this CTA's tile:
//   gates[64 x 128] = A[64 x ktot] * W^T  (A = [seg0 | seg1], W = [w0 | w1] along K)
// then cell update with per-thread c state, h written to hout.
__device__ __forceinline__ void run_layer(
    char* smem,
    const float* __restrict__ a0, long a0s, int k0,
    const float* __restrict__ a1, long a1s,
    const float* __restrict__ w0, int w0s,
    const float* __restrict__ w1, int w1s,
    int ktot,
    const float* __restrict__ biasL,   // 128 floats in smem: [4][32] (b_ih+b_hh)
    float* cst,                        // [8] per-thread c state
    float* __restrict__ hout,          // &g_hX[wb][0][0]
    int mb, int hb, bool extra_tanh)
{
    float* A_s = (float*)smem;                      // [64][36]
    float* B_s = (float*)(smem + 64 * 36 * 4);      // [128][36]
    const int tid  = threadIdx.x;
    const int lane = tid & 31, wid = tid >> 5;
    const int wm = wid >> 2, wn = wid & 3;          // 2 x 4 warp grid; wn = gate
    const int r4 = lane >> 2, kc = lane & 3;
    const int lr  = tid >> 3;                        // loader row base (0..31)
    const int lco = (tid & 7) << 2;                  // loader col offset (0,4,..,28)
    const int hbase = hb * HB;

    float acc[2][4][4];
    #pragma unroll
    for (int i = 0; i < 2; i++)
        #pragma unroll
        for (int j = 0; j < 4; j++)
            #pragma unroll
            for (int q = 0; q < 4; q++) acc[i][j][q] = 0.f;

    const int nt = ktot / KT;
    float4 pa0, pa1, pb[4];

    auto load_tile = [&](int k) {
        const float* asrc; long ars; int ak;
        if (k < k0) { asrc = a0; ars = a0s; ak = k; }
        else        { asrc = a1; ars = a1s; ak = k - k0; }
        pa0 = __ldcg((const float4*)(asrc + (long)lr * ars + ak + lco));
        pa1 = __ldcg((const float4*)(asrc + (long)(lr + 32) * ars + ak + lco));
        const float* wsrc; int ws, wk;
        if (k < k0) { wsrc = w0; ws = w0s; wk = k; }
        else        { wsrc = w1; ws = w1s; wk = k - k0; }
        #pragma unroll
        for (int i = 0; i < 4; i++) {
            int r = lr + i * 32;                       // 0..127 gate col
            long wrow = (long)((r >> 5) * H_ + hbase + (r & 31)) * ws;
            pb[i] = __ldg((const float4*)(wsrc + wrow + wk + lco));
        }
    };

    auto store_tile = [&]() {
        *(uint4*)(A_s + lr * 36 + lco)        = cvt4(pa0);
        *(uint4*)(A_s + (lr + 32) * 36 + lco) = cvt4(pa1);
        #pragma unroll
        for (int i = 0; i < 4; i++)
            *(uint4*)(B_s + (lr + i * 32) * 36 + lco) = cvt4(pb[i]);
    };

    load_tile(0);
    for (int kt = 0; kt < nt; kt++) {
        store_tile();
        __syncthreads();
        if (kt + 1 < nt) load_tile((kt + 1) * KT);   // overlap next-tile GMEM loads with MMA
        const unsigned* Au = (const unsigned*)A_s;
        const unsigned* Bu = (const unsigned*)B_s;
        #pragma unroll
        for (int kk = 0; kk < 4; kk++) {
            unsigned a[2][4];
            #pragma unroll
            for (int mi = 0; mi < 2; mi++) {
                int ar = (wm * 32 + mi * 16 + r4) * 36 + kk * 8 + kc;
                a[mi][0] = Au[ar];
                a[mi][1] = Au[ar + 8 * 36];
                a[mi][2] = Au[ar + 4];
                a[mi][3] = Au[ar + 8 * 36 + 4];
            }
            #pragma unroll
            for (int ni = 0; ni < 4; ni++) {
                int br = (wn * 32 + ni * 8 + r4) * 36 + kk * 8 + kc;
                unsigned b0 = Bu[br], b1 = Bu[br + 4];
                mma_tf32(acc[0][ni], a[0], b0, b1);
                mma_tf32(acc[1][ni], a[1], b0, b1);
            }
        }
        __syncthreads();
    }

    // Epilogue: gates -> smem (reuse A_s/B_s region), then cell update
    float* gates = (float*)smem;                    // [4][64][33]
    #pragma unroll
    for (int mi = 0; mi < 2; mi++)
        #pragma unroll
        for (int ni = 0; ni < 4; ni++) {
            int row = wm * 32 + mi * 16 + r4;
            int col = ni * 8 + kc * 2;
            float* gb = gates + wn * (64 * 33) + row * 33 + col;
            gb[0]          = acc[mi][ni][0];
            gb[1]          = acc[mi][ni][1];
            gb[8 * 33]     = acc[mi][ni][2];
            gb[8 * 33 + 1] = acc[mi][ni][3];
        }
    __syncthreads();

    #pragma unroll
    for (int j = 0; j < 8; j++) {
        int idx = j * NTH + tid;
        int row = idx >> 5, col = idx & 31;
        float gi = gates[0 * 2112 + row * 33 + col] + biasL[0 * 32 + col];
        float gf = gates[1 * 2112 + row * 33 + col] + biasL[1 * 32 + col];
        float gg = gates[2 * 2112 + row * 33 + col] + biasL[2 * 32 + col];
        float go = gates[3 * 2112 + row * 33 + col] + biasL[3 * 32 + col];
        float ii = sigmoidf_(gi);
        float ff = sigmoidf_(gf);
        float g2 = tanhf(gg);
        float oo = sigmoidf_(go);
        float cn = ff * cst[j] + ii * g2;
        cst[j] = cn;
        float h = oo * tanhf(cn);
        if (extra_tanh) h = tanhf(h);
        __stcg(&hout[(long)(mb * MT + row) * H_ + hbase + col], h);
    }
    // next smem overwrite happens after the caller's grid_barrier (starts with __syncthreads)
}

__global__ void __launch_bounds__(NTH, 1) lstm_fused(
    const float* __restrict__ y,
    const float* __restrict__ Wih1, const float* __restrict__ Whh1,
    const float* __restrict__ bih1, const float* __restrict__ bhh1,
    const float* __restrict__ Wih2, const float* __restrict__ Whh2,
    const float* __restrict__ bih2, const float* __restrict__ bhh2,
    const float* __restrict__ Wout, const float* __restrict__ bout,
    float* __restrict__ out)
{
    extern __shared__ char smem[];
    const int tid = threadIdx.x;
    const int mb = blockIdx.x >> 5;   // 0..3
    const int hb = blockIdx.x & 31;   // 0..31
    float* bias_s = (float*)(smem + 4 * 64 * 33 * 4);  // [2][4][32]

    // zero initial h state (buffer 0) for this CTA's slice
    for (int i = tid; i < MT * HB; i += NTH) {
        int r = i >> 5, c = i & 31;
        g_h1[0][mb * MT + r][hb * HB + c] = 0.f;
        g_h2[0][mb * MT + r][hb * HB + c] = 0.f;
    }
    // combined biases, both layers (constant over time)
    {
        int l = tid >> 7;
        int g = (tid >> 5) & 3;
        int u = tid & 31;
        int grow = g * H_ + hb * HB + u;
        bias_s[tid] = (l == 0) ? (bih1[grow] + bhh1[grow]) : (bih2[grow] + bhh2[grow]);
    }
    float c1[8], c2[8];
    #pragma unroll
    for (int j = 0; j < 8; j++) { c1[j] = 0.f; c2[j] = 0.f; }
    __syncthreads();
    grid_barrier();

    for (int t = 0; t < T_; t++) {
        int rb = t & 1, wb = rb ^ 1;
        // layer 1: A = [ x_t (F) | h1_prev (H) ], W = [ Wih1 | Whh1 ]
        run_layer(smem,
                  y + (long)(mb * MT) * (T_ * F_) + (long)t * F_, (long)(T_ * F_), F_,
                  &g_h1[rb][mb * MT][0], (long)H_,
                  Wih1, F_, Whh1, H_,
                  F_ + H_,
                  bias_s, c1, &g_h1[wb][0][0], mb, hb, false);
        grid_barrier();
        // layer 2: A = [ h1_new (H) | h2_prev (H) ], W = [ Wih2 | Whh2 ]
        run_layer(smem,
                  &g_h1[wb][mb * MT][0], (long)H_, H_,
                  &g_h2[rb][mb * MT][0], (long)H_,
                  Wih2, H_, Whh2, H_,
                  2 * H_,
                  bias_s + 128, c2, &g_h2[wb][0][0], mb, hb, true);
        grid_barrier();
    }

    // Output projection on the last timestep: h2 final lives in buffer 0 (T even).
    // 128 CTAs x 256 threads == 32768 == B*C: one output element per thread.
    {
        int gid = blockIdx.x * NTH + tid;
        int b = gid >> 7, cc = gid & 127;
        float acc = __ldg(&bout[cc]);
        const float4* hr = (const float4*)&g_h2[0][b][0];
        const float4* wr = (const float4*)&Wout[(long)cc * H_];
        #pragma unroll 8
        for (int k = 0; k < H_ / 4; k++) {
            float4 hv = __ldcg(hr + k);
            float4 wv = __ldg(wr + k);
            acc += hv.x * wv.x + hv.y * wv.y + hv.z * wv.z + hv.w * wv.w;
        }
        out[gid] = fmaxf(acc, 0.f);
    }
}

extern "C" void kernel_launch(void* const* d_in, const int* in_sizes, int n_in,
                              void* d_out, int out_size) {
    const float* y    = (const float*)d_in[0];
    const float* Wih1 = (const float*)d_in[1];
    const float* Whh1 = (const float*)d_in[2];
    const float* bih1 = (const float*)d_in[3];
    const float* bhh1 = (const float*)d_in[4];
    const float* Wih2 = (const float*)d_in[5];
    const float* Whh2 = (const float*)d_in[6];
    const float* bih2 = (const float*)d_in[7];
    const float* bhh2 = (const float*)d_in[8];
    const float* Wout = (const float*)d_in[9];
    const float* bout = (const float*)d_in[10];
    float* out = (float*)d_out;

    const int smem_bytes = 4 * 64 * 33 * 4 + 2 * 4 * 32 * 4;  // gates region + biases
    lstm_fused<<<NCTA, NTH, smem_bytes>>>(y, Wih1, Whh1, bih1, bhh1,
                                          Wih2, Whh2, bih2, bhh2,
                                          Wout, bout, out);
}

// round 3
// speedup vs baseline: 1.3304x; 1.3304x over previous
#include <cuda_runtime.h>
#include <math.h>
#include <stdint.h>

// Problem dims
#define B_  256
#define T_  512
#define F_  256
#define H_  1024
#define C_  128

// Tiling
#define NCTA 128     // 4 m-blocks x 32 h-blocks
#define NTH  256
#define MT   64      // batch rows per CTA
#define HB   32      // hidden units per CTA (-> 128 gate cols)
#define KT   32      // K tile
#define NKT1 40      // (F+H)/KT
#define NKT2 64      // (2H)/KT

// Persistent scratch (no allocations allowed)
__device__ __align__(16) float g_h1[2][B_][H_];
__device__ __align__(16) float g_h2[2][B_][H_];
__device__ __align__(16) float g_y[(long)B_ * T_ * F_];
// Packed, tf32-rounded weights in mma-fragment order:
// [hb][kt][wn][ni][kk2][lane] float4  -> 4096 floats per (hb,kt)
__device__ __align__(16) float g_Wp1[32L * NKT1 * 4096];
__device__ __align__(16) float g_Wp2[32L * NKT2 * 4096];
__device__ unsigned g_cnt = 0;
__device__ volatile unsigned g_gen = 0;

__device__ __forceinline__ unsigned f2tf32(float x) {
    unsigned r;
    asm("cvt.rna.tf32.f32 %0, %1;" : "=r"(r) : "f"(x));
    return r;
}

__device__ __forceinline__ void grid_barrier() {
    __syncthreads();
    if (threadIdx.x == 0) {
        unsigned my = g_gen;
        __threadfence();
        if (atomicAdd(&g_cnt, 1u) == NCTA - 1) {
            g_cnt = 0;
            __threadfence();
            g_gen = my + 1;
        } else {
            while (g_gen == my) { }
            __threadfence();
        }
    }
    __syncthreads();
}

__device__ __forceinline__ void mma_tf32(float* c, const unsigned* a, unsigned b0, unsigned b1) {
    asm volatile(
        "mma.sync.aligned.m16n8k8.row.col.f32.tf32.tf32.f32 "
        "{%0,%1,%2,%3}, {%4,%5,%6,%7}, {%8,%9}, {%0,%1,%2,%3};"
        : "+f"(c[0]), "+f"(c[1]), "+f"(c[2]), "+f"(c[3])
        : "r"(a[0]), "r"(a[1]), "r"(a[2]), "r"(a[3]), "r"(b0), "r"(b1));
}

__device__ __forceinline__ void cp16(uint32_t dst, const void* src) {
    asm volatile("cp.async.cg.shared.global [%0], [%1], 16;" :: "r"(dst), "l"(src));
}
#define CP_COMMIT()  asm volatile("cp.async.commit_group;" ::: "memory")
#define CP_WAIT0()   asm volatile("cp.async.wait_group 0;" ::: "memory")

__device__ __forceinline__ float sigmoidf_(float x) { return 1.f / (1.f + expf(-x)); }

// ---------------- prep kernel: pack weights + convert y (time-invariant work) --------
__global__ void prep_kernel(const float* __restrict__ y,
                            const float* __restrict__ Wih1, const float* __restrict__ Whh1,
                            const float* __restrict__ Wih2, const float* __restrict__ Whh2)
{
    long tid = (long)blockIdx.x * blockDim.x + threadIdx.x;
    long nth = (long)gridDim.x * blockDim.x;

    // y -> tf32-rounded copy
    for (long i = tid; i < (long)B_ * T_ * F_; i += nth)
        g_y[i] = __uint_as_float(f2tf32(y[i]));

    // pack layer 1: one float4 per work item
    const long n1 = 32L * NKT1 * 4 * 4 * 2 * 32;
    for (long i = tid; i < n1; i += nth) {
        int lane = (int)(i & 31); long r = i >> 5;
        int kk2 = (int)(r & 1); r >>= 1;
        int ni  = (int)(r & 3); r >>= 2;
        int wn  = (int)(r & 3); r >>= 2;
        int kt  = (int)(r % NKT1);
        int hb  = (int)(r / NKT1);
        int ncol = wn * 32 + ni * 8 + (lane >> 2);
        long wrow = (long)((ncol >> 5) * H_ + hb * 32 + (ncol & 31));
        int kb = kt * KT + kk2 * 16 + (lane & 3);
        float4 v;
        if (kb < F_) {
            const float* s = Wih1 + wrow * F_ + kb;
            v.x = s[0]; v.y = s[4]; v.z = s[8]; v.w = s[12];
        } else {
            const float* s = Whh1 + wrow * H_ + (kb - F_);
            v.x = s[0]; v.y = s[4]; v.z = s[8]; v.w = s[12];
        }
        uint4 t;
        t.x = f2tf32(v.x); t.y = f2tf32(v.y); t.z = f2tf32(v.z); t.w = f2tf32(v.w);
        ((uint4*)g_Wp1)[i] = t;
    }

    // pack layer 2
    const long n2 = 32L * NKT2 * 4 * 4 * 2 * 32;
    for (long i = tid; i < n2; i += nth) {
        int lane = (int)(i & 31); long r = i >> 5;
        int kk2 = (int)(r & 1); r >>= 1;
        int ni  = (int)(r & 3); r >>= 2;
        int wn  = (int)(r & 3); r >>= 2;
        int kt  = (int)(r % NKT2);
        int hb  = (int)(r / NKT2);
        int ncol = wn * 32 + ni * 8 + (lane >> 2);
        long wrow = (long)((ncol >> 5) * H_ + hb * 32 + (ncol & 31));
        int kb = kt * KT + kk2 * 16 + (lane & 3);
        float4 v;
        if (kb < H_) {
            const float* s = Wih2 + wrow * H_ + kb;
            v.x = s[0]; v.y = s[4]; v.z = s[8]; v.w = s[12];
        } else {
            const float* s = Whh2 + wrow * H_ + (kb - H_);
            v.x = s[0]; v.y = s[4]; v.z = s[8]; v.w = s[12];
        }
        uint4 t;
        t.x = f2tf32(v.x); t.y = f2tf32(v.y); t.z = f2tf32(v.z); t.w = f2tf32(v.w);
        ((uint4*)g_Wp2)[i] = t;
    }
}

// ---------------- main persistent kernel ----------------

// smem layout:
//   A buffers: 2 x [64][36] floats at offsets 0 and 9216 bytes
//   gates (epilogue, reuses A region): [4][64][33] floats (33792 B)
//   bias:  at 33792, 256 floats
#define ABUF_BYTES (64 * 36 * 4)
#define BIAS_OFF   (4 * 64 * 33 * 4)
#define SMEM_BYTES (BIAS_OFF + 2 * 4 * 32 * 4)

struct LayerCtx {
    const float* a0; long a0s; int ks0;   // tiles from a0: kt < ks0
    const float* a1; long a1s;
    const float4* wpack;                  // per-hb base, float4 units
    int nt;
};

__device__ __forceinline__ void run_layer(
    char* smem, uint32_t smem_u32, const LayerCtx& L,
    const float* __restrict__ biasL, float* cst,
    float* __restrict__ hout, int mb, int hb, bool extra_tanh)
{
    const int tid  = threadIdx.x;
    const int lane = tid & 31, wid = tid >> 5;
    const int wm = wid >> 2, wn = wid & 3;
    const int r4 = lane >> 2, kc = lane & 3;
    const int lr  = tid >> 3;
    const int lco = (tid & 7) << 2;
    const int hbase = hb * HB;

    const unsigned* Au0 = (const unsigned*)smem;
    const unsigned* Au1 = (const unsigned*)(smem + ABUF_BYTES);
    const uint32_t dst0 = smem_u32 + (lr * 36 + lco) * 4;
    const uint32_t dst0b = dst0 + 32 * 36 * 4;
    const uint32_t dst1 = dst0 + ABUF_BYTES;
    const uint32_t dst1b = dst0b + ABUF_BYTES;

    float acc[2][4][4];
    #pragma unroll
    for (int i = 0; i < 2; i++)
        #pragma unroll
        for (int j = 0; j < 4; j++)
            #pragma unroll
            for (int q = 0; q < 4; q++) acc[i][j][q] = 0.f;

    auto issueA = [&](int kt, uint32_t d0, uint32_t d1) {
        const float* s; long st;
        if (kt < L.ks0) { s = L.a0 + (long)lr * L.a0s + kt * KT + lco; st = L.a0s; }
        else            { s = L.a1 + (long)lr * L.a1s + (kt - L.ks0) * KT + lco; st = L.a1s; }
        cp16(d0, s);
        cp16(d1, s + 32 * st);
        CP_COMMIT();
    };

    const uint4* wbase = (const uint4*)L.wpack + (long)wn * 256 + lane;
    auto loadB = [&](int kt, uint4* bb) {
        const uint4* p = wbase + (long)kt * 1024;
        #pragma unroll
        for (int j = 0; j < 8; j++) bb[j] = __ldg(p + 32 * j);
    };

    auto mma_tile = [&](const unsigned* Au, const uint4* bb) {
        const int abase = (wm * 32 + r4) * 36 + kc;
        #pragma unroll
        for (int kk = 0; kk < 4; kk++) {
            unsigned a[2][4];
            #pragma unroll
            for (int mi = 0; mi < 2; mi++) {
                int ar = abase + mi * 16 * 36 + kk * 8;
                a[mi][0] = Au[ar];
                a[mi][1] = Au[ar + 8 * 36];
                a[mi][2] = Au[ar + 4];
                a[mi][3] = Au[ar + 8 * 36 + 4];
            }
            #pragma unroll
            for (int ni = 0; ni < 4; ni++) {
                uint4 w = bb[ni * 2 + (kk >> 1)];
                unsigned b0 = (kk & 1) ? w.z : w.x;
                unsigned b1 = (kk & 1) ? w.w : w.y;
                mma_tf32(acc[0][ni], a[0], b0, b1);
                mma_tf32(acc[1][ni], a[1], b0, b1);
            }
        }
    };

    uint4 bb0[8], bb1[8];
    issueA(0, dst0, dst0b);
    loadB(0, bb0);
    const int nt = L.nt;   // always even
    for (int kt = 0; kt < nt; kt += 2) {
        CP_WAIT0();
        __syncthreads();
        if (kt + 1 < nt) { issueA(kt + 1, dst1, dst1b); loadB(kt + 1, bb1); }
        mma_tile(Au0, bb0);
        if (kt + 1 < nt) {
            CP_WAIT0();
            __syncthreads();
            if (kt + 2 < nt) { issueA(kt + 2, dst0, dst0b); loadB(kt + 2, bb0); }
            mma_tile(Au1, bb1);
        }
    }
    __syncthreads();   // before reusing smem as gates region

    // Epilogue: gates -> smem, then cell update
    float* gates = (float*)smem;   // [4][64][33]
    #pragma unroll
    for (int mi = 0; mi < 2; mi++)
        #pragma unroll
        for (int ni = 0; ni < 4; ni++) {
            int row = wm * 32 + mi * 16 + r4;
            int col = ni * 8 + kc * 2;
            float* gb = gates + wn * (64 * 33) + row * 33 + col;
            gb[0]          = acc[mi][ni][0];
            gb[1]          = acc[mi][ni][1];
            gb[8 * 33]     = acc[mi][ni][2];
            gb[8 * 33 + 1] = acc[mi][ni][3];
        }
    __syncthreads();

    #pragma unroll
    for (int j = 0; j < 8; j++) {
        int idx = j * NTH + tid;
        int row = idx >> 5, col = idx & 31;
        float gi = gates[0 * 2112 + row * 33 + col] + biasL[0 * 32 + col];
        float gf = gates[1 * 2112 + row * 33 + col] + biasL[1 * 32 + col];
        float gg = gates[2 * 2112 + row * 33 + col] + biasL[2 * 32 + col];
        float go = gates[3 * 2112 + row * 33 + col] + biasL[3 * 32 + col];
        float ii = sigmoidf_(gi);
        float ff = sigmoidf_(gf);
        float g2 = tanhf(gg);
        float oo = sigmoidf_(go);
        float cn = ff * cst[j] + ii * g2;
        cst[j] = cn;
        float h = oo * tanhf(cn);
        if (extra_tanh) h = tanhf(h);
        // store tf32-rounded: identical mma input, skips per-step cvt on A path
        __stcg(&hout[(long)(mb * MT + row) * H_ + hbase + col],
               __uint_as_float(f2tf32(h)));
    }
}

__global__ void __launch_bounds__(NTH, 1) lstm_fused(
    const float* __restrict__ bih1, const float* __restrict__ bhh1,
    const float* __restrict__ bih2, const float* __restrict__ bhh2,
    const float* __restrict__ Wout, const float* __restrict__ bout,
    float* __restrict__ out)
{
    extern __shared__ char smem[];
    uint32_t smem_u32;
    asm("{ .reg .u64 t; cvta.to.shared.u64 t, %1; cvt.u32.u64 %0, t; }"
        : "=r"(smem_u32) : "l"(smem));
    const int tid = threadIdx.x;
    const int mb = blockIdx.x >> 5;   // 0..3
    const int hb = blockIdx.x & 31;   // 0..31
    float* bias_s = (float*)(smem + BIAS_OFF);  // [2][4][32]

    // zero initial h state (buffer 0) for this CTA's slice
    for (int i = tid; i < MT * HB; i += NTH) {
        int r = i >> 5, c = i & 31;
        g_h1[0][mb * MT + r][hb * HB + c] = 0.f;
        g_h2[0][mb * MT + r][hb * HB + c] = 0.f;
    }
    // combined biases, both layers
    {
        int l = tid >> 7;
        int g = (tid >> 5) & 3;
        int u = tid & 31;
        int grow = g * H_ + hb * HB + u;
        bias_s[tid] = (l == 0) ? (bih1[grow] + bhh1[grow]) : (bih2[grow] + bhh2[grow]);
    }
    float c1[8], c2[8];
    #pragma unroll
    for (int j = 0; j < 8; j++) { c1[j] = 0.f; c2[j] = 0.f; }
    __syncthreads();
    grid_barrier();

    const float4* wp1 = (const float4*)g_Wp1 + (long)hb * NKT1 * 1024;
    const float4* wp2 = (const float4*)g_Wp2 + (long)hb * NKT2 * 1024;

    for (int t = 0; t < T_; t++) {
        int rb = t & 1, wb = rb ^ 1;
        {
            LayerCtx L;
            L.a0 = g_y + (long)(mb * MT) * (T_ * F_) + (long)t * F_;
            L.a0s = (long)(T_ * F_);
            L.ks0 = F_ / KT;                 // 8
            L.a1 = &g_h1[rb][mb * MT][0];
            L.a1s = (long)H_;
            L.wpack = wp1;
            L.nt = NKT1;
            run_layer(smem, smem_u32, L, bias_s, c1, &g_h1[wb][0][0], mb, hb, false);
        }
        grid_barrier();
        {
            LayerCtx L;
            L.a0 = &g_h1[wb][mb * MT][0];
            L.a0s = (long)H_;
            L.ks0 = H_ / KT;                 // 32
            L.a1 = &g_h2[rb][mb * MT][0];
            L.a1s = (long)H_;
            L.wpack = wp2;
            L.nt = NKT2;
            run_layer(smem, smem_u32, L, bias_s + 128, c2, &g_h2[wb][0][0], mb, hb, true);
        }
        grid_barrier();
    }

    // Output projection: h2 final lives in buffer 0 (T even).
    {
        int gid = blockIdx.x * NTH + tid;
        int b = gid >> 7, cc = gid & 127;
        float acc = __ldg(&bout[cc]);
        const float4* hr = (const float4*)&g_h2[0][b][0];
        const float4* wr = (const float4*)&Wout[(long)cc * H_];
        #pragma unroll 8
        for (int k = 0; k < H_ / 4; k++) {
            float4 hv = __ldcg(hr + k);
            float4 wv = __ldg(wr + k);
            acc += hv.x * wv.x + hv.y * wv.y + hv.z * wv.z + hv.w * wv.w;
        }
        out[gid] = fmaxf(acc, 0.f);
    }
}

extern "C" void kernel_launch(void* const* d_in, const int* in_sizes, int n_in,
                              void* d_out, int out_size) {
    const float* y    = (const float*)d_in[0];
    const float* Wih1 = (const float*)d_in[1];
    const float* Whh1 = (const float*)d_in[2];
    const float* bih1 = (const float*)d_in[3];
    const float* bhh1 = (const float*)d_in[4];
    const float* Wih2 = (const float*)d_in[5];
    const float* Whh2 = (const float*)d_in[6];
    const float* bih2 = (const float*)d_in[7];
    const float* bhh2 = (const float*)d_in[8];
    const float* Wout = (const float*)d_in[9];
    const float* bout = (const float*)d_in[10];
    float* out = (float*)d_out;

    prep_kernel<<<2048, 256>>>(y, Wih1, Whh1, Wih2, Whh2);
    lstm_fused<<<NCTA, NTH, SMEM_BYTES>>>(bih1, bhh1, bih2, bhh2, Wout, bout, out);
}